// round 16
// baseline (speedup 1.0000x reference)
#include <cuda_runtime.h>
#include <cuda_bf16.h>
#include <cstdint>
#include <stdint.h>

#define NB 4
#define NC 64
#define NP 8192
#define KNBR 20
#define NPT (NB*NP)
#define NSAMP (NPT*KNBR)
#define FULLMASK 0xffffffffu

__device__ __align__(16) float g_f[NPT*NC];
__device__ float g_sq[NPT];
__device__ int   g_idx[NSAMP];
__device__ __align__(16) float g_P[NPT*NC];
__device__ __align__(16) float g_Q[NPT*NC];
__device__ float g_W1a[64*64];
__device__ float g_W1d[64*64];
__device__ float g_stats1[128];
__device__ float g_stats2[128];
__device__ float g_scale1[64], g_shift1[64];
__device__ float g_scale2[64], g_shift2[64];
__device__ __align__(16) float g_gmax[NPT*64];
__device__ __align__(16) float g_gmin[NPT*64];

// ---------------- prep ----------------
__global__ void k_prep(const float* __restrict__ W1){
  int o = blockIdx.x, c = threadIdx.x;
  float a  = W1[o*128 + c];
  float bb = W1[o*128 + 64 + c];
  g_W1a[o*64+c] = a;
  g_W1d[o*64+c] = bb - a;
  if(o == 0){
    g_stats1[c] = 0.f; g_stats1[64+c] = 0.f;
    g_stats2[c] = 0.f; g_stats2[64+c] = 0.f;
  }
}

// ---------------- transpose + sq ----------------
__global__ void k_transpose(const float* __restrict__ x){
  int b = blockIdx.y;
  int n = blockIdx.x*256 + threadIdx.x;
  const float* xb = x + b*NC*NP;
  float4* f4 = reinterpret_cast<float4*>(g_f) + (b*NP + n)*16;
  float s = 0.f;
  #pragma unroll
  for(int c4=0; c4<16; c4++){
    float4 v;
    v.x = xb[(4*c4+0)*NP + n];
    v.y = xb[(4*c4+1)*NP + n];
    v.z = xb[(4*c4+2)*NP + n];
    v.w = xb[(4*c4+3)*NP + n];
    s += v.x*v.x + v.y*v.y + v.z*v.z + v.w*v.w;
    f4[c4] = v;
  }
  g_sq[b*NP+n] = s;
}

// ---------------- knn v4: scalar 8x8, vectorized loads, d-space ----------------
#define TILE_C 256
#define SB_STR 264
#define KN4_SMEM ((4096 + 64*SB_STR + 256 + 64)*4)

#define KN_INSERT(cd, cm, j) do{ \
  float bv = (lane < KNBR) ? kd[j] : -INF; \
  int bl = lane; \
  _Pragma("unroll") \
  for(int off=16; off; off>>=1){ \
    float ov = __shfl_xor_sync(FULLMASK, bv, off); \
    int   ol = __shfl_xor_sync(FULLMASK, bl, off); \
    if(ov > bv || (ov == bv && ol < bl)){ bv = ov; bl = ol; } \
  } \
  if((cd) < bv && lane == bl){ kd[j] = (cd); ki[j] = (cm); } \
}while(0)

__global__ __launch_bounds__(256, 2) void k_knn(const float* __restrict__ x){
  extern __shared__ float sm[];
  float* sA   = sm;                    // [64 c][64 row]
  float* sB   = sm + 4096;             // [64 c][SB_STR cols]
  float* sQ   = sB + 64*SB_STR;        // [256] tile-col sq
  float* sqrS = sQ + 256;              // [64] row sq
  int t = threadIdx.x;
  int lane = t & 31, warp = t >> 5;
  int b = blockIdx.y;
  int rbase = blockIdx.x*64;
  const float* xb = x + (size_t)b*64*NP;
  const float INF = __int_as_float(0x7f800000);

  // load sA (c-major rows): consecutive threads -> consecutive rows, conflict-free
  {
    int row = t & 63, c0 = t >> 6;
    #pragma unroll
    for(int cc=0; cc<16; cc++){
      int c = c0 + cc*4;
      sA[c*64 + row] = xb[c*NP + rbase + row];
    }
    if(t < 64) sqrS[t] = g_sq[b*NP + rbase + t];
  }

  float kd[8]; int ki[8]; float wshift[8];
  #pragma unroll
  for(int j=0;j<8;j++){ kd[j]=INF; ki[j]=0; wshift[j]=INF; }

  for(int tile=0; tile<NP/TILE_C; tile++){
    int tb = tile*TILE_C;
    __syncthreads();   // prior sB/sQ reads complete
    // load sB: warp owns c rows {warp, warp+8,...}; lane -> 8 consecutive cols
    #pragma unroll
    for(int ci=0; ci<8; ci++){
      int c = warp + ci*8;
      const float4* src = reinterpret_cast<const float4*>(xb + c*NP + tb) + lane*2;
      float4 v0 = src[0], v1 = src[1];
      float4* dst = reinterpret_cast<float4*>(sB + c*SB_STR + lane*8);
      dst[0] = v0; dst[1] = v1;
    }
    sQ[t] = g_sq[b*NP + tb + t];
    __syncthreads();

    float sq8[8];
    {
      const float4* q4 = reinterpret_cast<const float4*>(sQ + lane*8);
      float4 q0 = q4[0], q1 = q4[1];
      sq8[0]=q0.x; sq8[1]=q0.y; sq8[2]=q0.z; sq8[3]=q0.w;
      sq8[4]=q1.x; sq8[5]=q1.y; sq8[6]=q1.z; sq8[7]=q1.w;
    }

    float acc[8][8];
    #pragma unroll
    for(int i=0;i<8;i++)
      #pragma unroll
      for(int j=0;j<8;j++) acc[i][j]=0.f;

    #pragma unroll 4
    for(int c=0;c<64;c++){
      float a8[8], w8[8];
      {
        const float4* a4 = reinterpret_cast<const float4*>(sA + c*64 + warp*8);
        float4 x0 = a4[0], x1 = a4[1];
        a8[0]=x0.x; a8[1]=x0.y; a8[2]=x0.z; a8[3]=x0.w;
        a8[4]=x1.x; a8[5]=x1.y; a8[6]=x1.z; a8[7]=x1.w;
      }
      {
        const float4* w4 = reinterpret_cast<const float4*>(sB + c*SB_STR + lane*8);
        float4 y0 = w4[0], y1 = w4[1];
        w8[0]=y0.x; w8[1]=y0.y; w8[2]=y0.z; w8[3]=y0.w;
        w8[4]=y1.x; w8[5]=y1.y; w8[6]=y1.z; w8[7]=y1.w;
      }
      #pragma unroll
      for(int i=0;i<8;i++)
        #pragma unroll
        for(int cc=0;cc<8;cc++) acc[i][cc] += a8[i]*w8[cc];
    }

    // selection: ballot in v-space vs round-up threshold; exact d inside walk
    #pragma unroll
    for(int j=0;j<8;j++){
      float v[8];
      #pragma unroll
      for(int cc=0;cc<8;cc++) v[cc] = fmaf(-2.f, acc[j][cc], sq8[cc]);
      float mn = v[0];
      #pragma unroll
      for(int cc=1;cc<8;cc++) mn = fminf(mn, v[cc]);
      float ws = wshift[j];
      if(__ballot_sync(FULLMASK, mn < ws)){
        float sqr_j = sqrS[warp*8 + j];
        #pragma unroll
        for(int cc=0;cc<8;cc++){
          unsigned m = __ballot_sync(FULLMASK, v[cc] < ws);
          while(m){
            int src = __ffs(m)-1; m &= m-1;
            float cdv = __shfl_sync(FULLMASK, v[cc], src);
            float cd = sqr_j + cdv;               // exact d-space value
            int cm = tb + src*8 + cc;
            KN_INSERT(cd, cm, j);
          }
        }
        float bv = (lane < KNBR) ? kd[j] : -INF;
        #pragma unroll
        for(int off=16; off; off>>=1) bv = fmaxf(bv, __shfl_xor_sync(FULLMASK, bv, off));
        wshift[j] = __fsub_ru(bv, sqr_j);         // >= exact worst - sqr: never under-admits
      }
    }
  }

  #pragma unroll
  for(int j=0;j<8;j++){
    int r = warp*8 + j;
    if(lane < KNBR) g_idx[(b*NP + rbase + r)*KNBR + lane] = ki[j];
  }
}

// ---------------- P/Q gemms ----------------
__global__ __launch_bounds__(256) void k_gemm64(int which){
  __shared__ float sA[64][68];
  __shared__ float sW[64][68];
  const float* __restrict__ Wm = which ? g_W1d : g_W1a;
  float* __restrict__ Out = which ? g_Q : g_P;
  int t = threadIdx.x;
  int b = blockIdx.y; int rbase = blockIdx.x*64;
  {
    int r = t>>2, cq = (t&3)*4;
    const float4* fr = reinterpret_cast<const float4*>(g_f) + (b*NP + rbase + r)*16;
    #pragma unroll
    for(int j=0;j<4;j++){
      float4 v = fr[cq+j];
      int c = (cq+j)*4;
      sA[c+0][r]=v.x; sA[c+1][r]=v.y; sA[c+2][r]=v.z; sA[c+3][r]=v.w;
    }
  }
  for(int i=t;i<4096;i+=256){ int o=i>>6, c=i&63; sW[c][o] = Wm[o*64+c]; }
  __syncthreads();
  int ty=t>>4, tx=t&15;
  float acc[4][4];
  #pragma unroll
  for(int i=0;i<4;i++)
    #pragma unroll
    for(int j=0;j<4;j++) acc[i][j]=0.f;
  #pragma unroll 4
  for(int c=0;c<64;c++){
    float4 a = *reinterpret_cast<const float4*>(&sA[c][ty*4]);
    float4 w = *reinterpret_cast<const float4*>(&sW[c][tx*4]);
    acc[0][0]+=a.x*w.x; acc[0][1]+=a.x*w.y; acc[0][2]+=a.x*w.z; acc[0][3]+=a.x*w.w;
    acc[1][0]+=a.y*w.x; acc[1][1]+=a.y*w.y; acc[1][2]+=a.y*w.z; acc[1][3]+=a.y*w.w;
    acc[2][0]+=a.z*w.x; acc[2][1]+=a.z*w.y; acc[2][2]+=a.z*w.z; acc[2][3]+=a.z*w.w;
    acc[3][0]+=a.w*w.x; acc[3][1]+=a.w*w.y; acc[3][2]+=a.w*w.z; acc[3][3]+=a.w*w.w;
  }
  float4* O4 = reinterpret_cast<float4*>(Out) + (b*NP + rbase)*16;
  #pragma unroll
  for(int i=0;i<4;i++)
    O4[(ty*4+i)*16 + tx] = make_float4(acc[i][0],acc[i][1],acc[i][2],acc[i][3]);
}

// ---------------- BN1 stats ----------------
__global__ __launch_bounds__(256) void k_stats1(){
  __shared__ float r1[4][64];
  __shared__ float r2[4][64];
  int t = threadIdx.x;
  int o = t & 63, sub = t >> 6;
  int base = blockIdx.x * 512;
  float s1 = 0.f, s2 = 0.f;
  for(int i = sub; i < 512; i += 4){
    int s = base + i;
    int bn = s / KNBR;
    int b = bn >> 13;
    int m = g_idx[s];
    float h = g_P[((b<<13)+m)*64 + o] + g_Q[bn*64 + o];
    s1 += h; s2 += h*h;
  }
  r1[sub][o] = s1; r2[sub][o] = s2;
  __syncthreads();
  if(sub == 0){
    atomicAdd(&g_stats1[o],    r1[0][o]+r1[1][o]+r1[2][o]+r1[3][o]);
    atomicAdd(&g_stats1[64+o], r2[0][o]+r2[1][o]+r2[2][o]+r2[3][o]);
  }
}

// ---------------- BN finalize ----------------
__global__ void k_bnfin(const float* __restrict__ g, const float* __restrict__ bb, int which){
  int o = threadIdx.x;
  const float* stats = which ? g_stats2 : g_stats1;
  const float inv = 1.f/(float)NSAMP;
  float mu  = stats[o]*inv;
  float var = stats[64+o]*inv - mu*mu;
  float rstd = rsqrtf(var + 1e-5f);
  float sc = g[o]*rstd;
  if(which){ g_scale2[o]=sc; g_shift2[o]=bb[o]-mu*sc; }
  else     { g_scale1[o]=sc; g_shift1[o]=bb[o]-mu*sc; }
}

// ---------------- conv2 + BN2 stats + max/min over k ----------------
#define PTS_PER 16
__global__ __launch_bounds__(256) void k_conv2(const float* __restrict__ W2){
  __shared__ float sA[64][68];
  __shared__ float sW[64][68];
  __shared__ float sScale[64], sShift[64];
  __shared__ float r1[4][64];
  __shared__ float r2[4][64];
  int t = threadIdx.x;
  const float INF = __int_as_float(0x7f800000);

  for(int i=t;i<4096;i+=256){ int o=i>>6, c=i&63; sW[c][o] = W2[o*64+c]; }
  if(t < 64){ sScale[t]=g_scale1[t]; sShift[t]=g_shift1[t]; }

  float ls1 = 0.f, ls2 = 0.f;
  float rmax[4], rmin[4];
  #pragma unroll
  for(int q=0;q<4;q++){ rmax[q]=-INF; rmin[q]=INF; }

  int ty=t>>4, tx=t&15;
  int myo = t & 63;
  int Sbase = blockIdx.x * (PTS_PER*KNBR);
  int pbase = blockIdx.x * PTS_PER;
  float* sH = &sA[0][0];

  for(int st=0; st<5; st++){
    __syncthreads();
    {
      int sl = t>>2, cq = (t&3)*4;
      int s = Sbase + st*64 + sl;
      int bn = s / KNBR;
      int b = bn >> 13;
      int m = g_idx[s];
      const float4* Pm = reinterpret_cast<const float4*>(g_P) + ((b<<13)+m)*16;
      const float4* Qn = reinterpret_cast<const float4*>(g_Q) + bn*16;
      #pragma unroll
      for(int j=0;j<4;j++){
        int cc = (cq+j)*4;
        float4 p = Pm[cq+j]; float4 q = Qn[cq+j];
        float v0=(p.x+q.x)*sScale[cc+0]+sShift[cc+0]; v0 = v0>=0.f? v0 : 0.2f*v0;
        float v1=(p.y+q.y)*sScale[cc+1]+sShift[cc+1]; v1 = v1>=0.f? v1 : 0.2f*v1;
        float v2=(p.z+q.z)*sScale[cc+2]+sShift[cc+2]; v2 = v2>=0.f? v2 : 0.2f*v2;
        float v3=(p.w+q.w)*sScale[cc+3]+sShift[cc+3]; v3 = v3>=0.f? v3 : 0.2f*v3;
        sA[cc+0][sl]=v0; sA[cc+1][sl]=v1; sA[cc+2][sl]=v2; sA[cc+3][sl]=v3;
      }
    }
    __syncthreads();

    float acc[4][4];
    #pragma unroll
    for(int i=0;i<4;i++)
      #pragma unroll
      for(int j=0;j<4;j++) acc[i][j]=0.f;
    #pragma unroll 4
    for(int c=0;c<64;c++){
      float4 a = *reinterpret_cast<const float4*>(&sA[c][ty*4]);
      float4 w = *reinterpret_cast<const float4*>(&sW[c][tx*4]);
      acc[0][0]+=a.x*w.x; acc[0][1]+=a.x*w.y; acc[0][2]+=a.x*w.z; acc[0][3]+=a.x*w.w;
      acc[1][0]+=a.y*w.x; acc[1][1]+=a.y*w.y; acc[1][2]+=a.y*w.z; acc[1][3]+=a.y*w.w;
      acc[2][0]+=a.z*w.x; acc[2][1]+=a.z*w.y; acc[2][2]+=a.z*w.z; acc[2][3]+=a.z*w.w;
      acc[3][0]+=a.w*w.x; acc[3][1]+=a.w*w.y; acc[3][2]+=a.w*w.z; acc[3][3]+=a.w*w.w;
    }
    __syncthreads();
    #pragma unroll
    for(int i=0;i<4;i++)
      #pragma unroll
      for(int j=0;j<4;j++)
        sH[(tx*4+j)*68 + ty*4+i] = acc[i][j];
    __syncthreads();
    #pragma unroll
    for(int q=0;q<4;q++){
      int p = (t>>6) + q*4;
      int s0 = p*KNBR - st*64;
      int s1e = s0 + KNBR;
      if(s0 < 0) s0 = 0;
      if(s1e > 64) s1e = 64;
      float mx = rmax[q], mn = rmin[q];
      for(int s=s0; s<s1e; s++){
        float v = sH[myo*68 + s];
        ls1 += v; ls2 += v*v;
        mx = fmaxf(mx, v); mn = fminf(mn, v);
      }
      rmax[q] = mx; rmin[q] = mn;
    }
  }

  #pragma unroll
  for(int q=0;q<4;q++){
    int p = (t>>6) + q*4;
    g_gmax[(pbase+p)*64 + myo] = rmax[q];
    g_gmin[(pbase+p)*64 + myo] = rmin[q];
  }
  r1[t>>6][myo] = ls1;
  r2[t>>6][myo] = ls2;
  __syncthreads();
  if(t < 64){
    atomicAdd(&g_stats2[t],    r1[0][t]+r1[1][t]+r1[2][t]+r1[3][t]);
    atomicAdd(&g_stats2[64+t], r2[0][t]+r2[1][t]+r2[2][t]+r2[3][t]);
  }
}

// ---------------- output ----------------
__global__ void k_out(float* __restrict__ out){
  int n = blockIdx.x*256 + threadIdx.x;
  int o = blockIdx.y, b = blockIdx.z;
  float s = g_scale2[o], tsh = g_shift2[o];
  const float* src = (s >= 0.f) ? g_gmax : g_gmin;
  float v = src[(b*NP + n)*64 + o];
  float h = s*v + tsh;
  out[(b*64 + o)*NP + n] = (h >= 0.f) ? h : 0.2f*h;
}

extern "C" void kernel_launch(void* const* d_in, const int* in_sizes, int n_in,
                              void* d_out, int out_size){
  const float* x  = (const float*)d_in[0];
  const float* W1 = (const float*)d_in[1];
  const float* g1 = (const float*)d_in[2];
  const float* b1 = (const float*)d_in[3];
  const float* W2 = (const float*)d_in[4];
  const float* g2 = (const float*)d_in[5];
  const float* b2 = (const float*)d_in[6];
  float* out = (float*)d_out;

  cudaFuncSetAttribute(k_knn, cudaFuncAttributeMaxDynamicSharedMemorySize, KN4_SMEM);

  k_prep<<<64, 64>>>(W1);
  k_transpose<<<dim3(NP/256, NB), 256>>>(x);
  k_gemm64<<<dim3(NP/64, NB), 256>>>(0);
  k_knn<<<dim3(NP/64, NB), 256, KN4_SMEM>>>(x);
  k_gemm64<<<dim3(NP/64, NB), 256>>>(1);
  k_stats1<<<NSAMP/512, 256>>>();
  k_bnfin<<<1, 64>>>(g1, b1, 0);
  k_conv2<<<NPT/PTS_PER, 256>>>(W2);
  k_bnfin<<<1, 64>>>(g2, b2, 1);
  k_out<<<dim3(NP/256, 64, NB), 256>>>(out);
}

// round 17
// speedup vs baseline: 1.2568x; 1.2568x over previous
#include <cuda_runtime.h>
#include <cuda_bf16.h>
#include <cstdint>
#include <stdint.h>

#define NB 4
#define NC 64
#define NP 8192
#define KNBR 20
#define NPT (NB*NP)
#define NSAMP (NPT*KNBR)
#define FULLMASK 0xffffffffu

__device__ __align__(16) float g_f[NPT*NC];
__device__ float g_sq[NPT];
__device__ int   g_idx[NSAMP];
__device__ __align__(16) float g_P[NPT*NC];
__device__ __align__(16) float g_Q[NPT*NC];
__device__ float g_W1a[64*64];
__device__ float g_W1d[64*64];
__device__ float g_stats1[128];
__device__ float g_stats2[128];
__device__ float g_scale1[64], g_shift1[64];
__device__ float g_scale2[64], g_shift2[64];
__device__ __align__(16) float g_gmax[NPT*64];
__device__ __align__(16) float g_gmin[NPT*64];

// ---------------- prep ----------------
__global__ void k_prep(const float* __restrict__ W1){
  int o = blockIdx.x, c = threadIdx.x;
  float a  = W1[o*128 + c];
  float bb = W1[o*128 + 64 + c];
  g_W1a[o*64+c] = a;
  g_W1d[o*64+c] = bb - a;
  if(o == 0){
    g_stats1[c] = 0.f; g_stats1[64+c] = 0.f;
    g_stats2[c] = 0.f; g_stats2[64+c] = 0.f;
  }
}

// ---------------- transpose + sq ----------------
__global__ void k_transpose(const float* __restrict__ x){
  int b = blockIdx.y;
  int n = blockIdx.x*256 + threadIdx.x;
  const float* xb = x + b*NC*NP;
  float4* f4 = reinterpret_cast<float4*>(g_f) + (b*NP + n)*16;
  float s = 0.f;
  #pragma unroll
  for(int c4=0; c4<16; c4++){
    float4 v;
    v.x = xb[(4*c4+0)*NP + n];
    v.y = xb[(4*c4+1)*NP + n];
    v.z = xb[(4*c4+2)*NP + n];
    v.w = xb[(4*c4+3)*NP + n];
    s += v.x*v.x + v.y*v.y + v.z*v.z + v.w*v.w;
    f4[c4] = v;
  }
  g_sq[b*NP+n] = s;
}

// ---------------- knn v5: 8 rows (broadcast) x 4 cols, 128-col tiles ----------------
#define TILE_C 128
#define SB_STR 132
#define KN5_SMEM ((4096 + 64*SB_STR + TILE_C + 64)*4)

#define KN_INSERT(cd, cm, j) do{ \
  float bv = (lane < KNBR) ? kd[j] : -INF; \
  int bl = lane; \
  _Pragma("unroll") \
  for(int off=16; off; off>>=1){ \
    float ov = __shfl_xor_sync(FULLMASK, bv, off); \
    int   ol = __shfl_xor_sync(FULLMASK, bl, off); \
    if(ov > bv || (ov == bv && ol < bl)){ bv = ov; bl = ol; } \
  } \
  if((cd) < bv && lane == bl){ kd[j] = (cd); ki[j] = (cm); } \
}while(0)

__global__ __launch_bounds__(256, 2) void k_knn(const float* __restrict__ x){
  extern __shared__ float sm[];
  float* sA   = sm;                    // [64 c][64 row]
  float* sB   = sm + 4096;             // [64 c][SB_STR cols]
  float* sQ   = sB + 64*SB_STR;        // [TILE_C] tile-col sq
  float* sqrS = sQ + TILE_C;           // [64] row sq
  int t = threadIdx.x;
  int lane = t & 31, warp = t >> 5;
  int b = blockIdx.y;
  int rbase = blockIdx.x*64;
  const float* xb = x + (size_t)b*64*NP;
  const float INF = __int_as_float(0x7f800000);

  // load sA (c-major rows): consecutive threads -> consecutive rows, conflict-free
  {
    int row = t & 63, c0 = t >> 6;
    #pragma unroll
    for(int cc=0; cc<16; cc++){
      int c = c0 + cc*4;
      sA[c*64 + row] = xb[c*NP + rbase + row];
    }
    if(t < 64) sqrS[t] = g_sq[b*NP + rbase + t];
  }

  float kd[8]; int ki[8]; float wshift[8];
  #pragma unroll
  for(int j=0;j<8;j++){ kd[j]=INF; ki[j]=0; wshift[j]=INF; }

  for(int tile=0; tile<NP/TILE_C; tile++){
    int tb = tile*TILE_C;
    __syncthreads();   // prior sB/sQ reads complete
    // load sB: warp owns c rows {warp, warp+8,...}; lane -> 4 consecutive cols
    #pragma unroll
    for(int ci=0; ci<8; ci++){
      int c = warp + ci*8;
      float4 v0 = *(reinterpret_cast<const float4*>(xb + c*NP + tb) + lane);
      *(reinterpret_cast<float4*>(sB + c*SB_STR) + lane) = v0;
    }
    if(t < TILE_C) sQ[t] = g_sq[b*NP + tb + t];
    __syncthreads();

    float sq4[4];
    {
      float4 q0 = *(reinterpret_cast<const float4*>(sQ) + lane);
      sq4[0]=q0.x; sq4[1]=q0.y; sq4[2]=q0.z; sq4[3]=q0.w;
    }

    float acc[8][4];
    #pragma unroll
    for(int i=0;i<8;i++)
      #pragma unroll
      for(int j=0;j<4;j++) acc[i][j]=0.f;

    #pragma unroll 4
    for(int c=0;c<64;c++){
      float a8[8], w4[4];
      {
        const float4* a4 = reinterpret_cast<const float4*>(sA + c*64 + warp*8);
        float4 x0 = a4[0], x1 = a4[1];   // broadcast across lanes
        a8[0]=x0.x; a8[1]=x0.y; a8[2]=x0.z; a8[3]=x0.w;
        a8[4]=x1.x; a8[5]=x1.y; a8[6]=x1.z; a8[7]=x1.w;
      }
      {
        float4 y0 = *(reinterpret_cast<const float4*>(sB + c*SB_STR) + lane);
        w4[0]=y0.x; w4[1]=y0.y; w4[2]=y0.z; w4[3]=y0.w;
      }
      #pragma unroll
      for(int i=0;i<8;i++)
        #pragma unroll
        for(int cc=0;cc<4;cc++) acc[i][cc] += a8[i]*w4[cc];
    }

    // selection: ballot in v-space vs round-up threshold; exact d inside walk
    #pragma unroll
    for(int j=0;j<8;j++){
      float v[4];
      #pragma unroll
      for(int cc=0;cc<4;cc++) v[cc] = fmaf(-2.f, acc[j][cc], sq4[cc]);
      float mn = fminf(fminf(v[0],v[1]), fminf(v[2],v[3]));
      float ws = wshift[j];
      if(__ballot_sync(FULLMASK, mn < ws)){
        float sqr_j = sqrS[warp*8 + j];
        #pragma unroll
        for(int cc=0;cc<4;cc++){
          unsigned m = __ballot_sync(FULLMASK, v[cc] < ws);
          while(m){
            int src = __ffs(m)-1; m &= m-1;
            float cdv = __shfl_sync(FULLMASK, v[cc], src);
            float cd = sqr_j + cdv;               // exact d-space value
            int cm = tb + src*4 + cc;
            KN_INSERT(cd, cm, j);
          }
        }
        float bv = (lane < KNBR) ? kd[j] : -INF;
        #pragma unroll
        for(int off=16; off; off>>=1) bv = fmaxf(bv, __shfl_xor_sync(FULLMASK, bv, off));
        wshift[j] = __fsub_ru(bv, sqr_j);         // never under-admits
      }
    }
  }

  #pragma unroll
  for(int j=0;j<8;j++){
    int r = warp*8 + j;
    if(lane < KNBR) g_idx[(b*NP + rbase + r)*KNBR + lane] = ki[j];
  }
}

// ---------------- P/Q gemms ----------------
__global__ __launch_bounds__(256) void k_gemm64(int which){
  __shared__ float sA[64][68];
  __shared__ float sW[64][68];
  const float* __restrict__ Wm = which ? g_W1d : g_W1a;
  float* __restrict__ Out = which ? g_Q : g_P;
  int t = threadIdx.x;
  int b = blockIdx.y; int rbase = blockIdx.x*64;
  {
    int r = t>>2, cq = (t&3)*4;
    const float4* fr = reinterpret_cast<const float4*>(g_f) + (b*NP + rbase + r)*16;
    #pragma unroll
    for(int j=0;j<4;j++){
      float4 v = fr[cq+j];
      int c = (cq+j)*4;
      sA[c+0][r]=v.x; sA[c+1][r]=v.y; sA[c+2][r]=v.z; sA[c+3][r]=v.w;
    }
  }
  for(int i=t;i<4096;i+=256){ int o=i>>6, c=i&63; sW[c][o] = Wm[o*64+c]; }
  __syncthreads();
  int ty=t>>4, tx=t&15;
  float acc[4][4];
  #pragma unroll
  for(int i=0;i<4;i++)
    #pragma unroll
    for(int j=0;j<4;j++) acc[i][j]=0.f;
  #pragma unroll 4
  for(int c=0;c<64;c++){
    float4 a = *reinterpret_cast<const float4*>(&sA[c][ty*4]);
    float4 w = *reinterpret_cast<const float4*>(&sW[c][tx*4]);
    acc[0][0]+=a.x*w.x; acc[0][1]+=a.x*w.y; acc[0][2]+=a.x*w.z; acc[0][3]+=a.x*w.w;
    acc[1][0]+=a.y*w.x; acc[1][1]+=a.y*w.y; acc[1][2]+=a.y*w.z; acc[1][3]+=a.y*w.w;
    acc[2][0]+=a.z*w.x; acc[2][1]+=a.z*w.y; acc[2][2]+=a.z*w.z; acc[2][3]+=a.z*w.w;
    acc[3][0]+=a.w*w.x; acc[3][1]+=a.w*w.y; acc[3][2]+=a.w*w.z; acc[3][3]+=a.w*w.w;
  }
  float4* O4 = reinterpret_cast<float4*>(Out) + (b*NP + rbase)*16;
  #pragma unroll
  for(int i=0;i<4;i++)
    O4[(ty*4+i)*16 + tx] = make_float4(acc[i][0],acc[i][1],acc[i][2],acc[i][3]);
}

// ---------------- BN1 stats ----------------
__global__ __launch_bounds__(256) void k_stats1(){
  __shared__ float r1[4][64];
  __shared__ float r2[4][64];
  int t = threadIdx.x;
  int o = t & 63, sub = t >> 6;
  int base = blockIdx.x * 512;
  float s1 = 0.f, s2 = 0.f;
  for(int i = sub; i < 512; i += 4){
    int s = base + i;
    int bn = s / KNBR;
    int b = bn >> 13;
    int m = g_idx[s];
    float h = g_P[((b<<13)+m)*64 + o] + g_Q[bn*64 + o];
    s1 += h; s2 += h*h;
  }
  r1[sub][o] = s1; r2[sub][o] = s2;
  __syncthreads();
  if(sub == 0){
    atomicAdd(&g_stats1[o],    r1[0][o]+r1[1][o]+r1[2][o]+r1[3][o]);
    atomicAdd(&g_stats1[64+o], r2[0][o]+r2[1][o]+r2[2][o]+r2[3][o]);
  }
}

// ---------------- BN finalize ----------------
__global__ void k_bnfin(const float* __restrict__ g, const float* __restrict__ bb, int which){
  int o = threadIdx.x;
  const float* stats = which ? g_stats2 : g_stats1;
  const float inv = 1.f/(float)NSAMP;
  float mu  = stats[o]*inv;
  float var = stats[64+o]*inv - mu*mu;
  float rstd = rsqrtf(var + 1e-5f);
  float sc = g[o]*rstd;
  if(which){ g_scale2[o]=sc; g_shift2[o]=bb[o]-mu*sc; }
  else     { g_scale1[o]=sc; g_shift1[o]=bb[o]-mu*sc; }
}

// ---------------- conv2 + BN2 stats + max/min over k ----------------
#define PTS_PER 16
__global__ __launch_bounds__(256) void k_conv2(const float* __restrict__ W2){
  __shared__ float sA[64][68];
  __shared__ float sW[64][68];
  __shared__ float sScale[64], sShift[64];
  __shared__ float r1[4][64];
  __shared__ float r2[4][64];
  int t = threadIdx.x;
  const float INF = __int_as_float(0x7f800000);

  for(int i=t;i<4096;i+=256){ int o=i>>6, c=i&63; sW[c][o] = W2[o*64+c]; }
  if(t < 64){ sScale[t]=g_scale1[t]; sShift[t]=g_shift1[t]; }

  float ls1 = 0.f, ls2 = 0.f;
  float rmax[4], rmin[4];
  #pragma unroll
  for(int q=0;q<4;q++){ rmax[q]=-INF; rmin[q]=INF; }

  int ty=t>>4, tx=t&15;
  int myo = t & 63;
  int Sbase = blockIdx.x * (PTS_PER*KNBR);
  int pbase = blockIdx.x * PTS_PER;
  float* sH = &sA[0][0];

  for(int st=0; st<5; st++){
    __syncthreads();
    {
      int sl = t>>2, cq = (t&3)*4;
      int s = Sbase + st*64 + sl;
      int bn = s / KNBR;
      int b = bn >> 13;
      int m = g_idx[s];
      const float4* Pm = reinterpret_cast<const float4*>(g_P) + ((b<<13)+m)*16;
      const float4* Qn = reinterpret_cast<const float4*>(g_Q) + bn*16;
      #pragma unroll
      for(int j=0;j<4;j++){
        int cc = (cq+j)*4;
        float4 p = Pm[cq+j]; float4 q = Qn[cq+j];
        float v0=(p.x+q.x)*sScale[cc+0]+sShift[cc+0]; v0 = v0>=0.f? v0 : 0.2f*v0;
        float v1=(p.y+q.y)*sScale[cc+1]+sShift[cc+1]; v1 = v1>=0.f? v1 : 0.2f*v1;
        float v2=(p.z+q.z)*sScale[cc+2]+sShift[cc+2]; v2 = v2>=0.f? v2 : 0.2f*v2;
        float v3=(p.w+q.w)*sScale[cc+3]+sShift[cc+3]; v3 = v3>=0.f? v3 : 0.2f*v3;
        sA[cc+0][sl]=v0; sA[cc+1][sl]=v1; sA[cc+2][sl]=v2; sA[cc+3][sl]=v3;
      }
    }
    __syncthreads();

    float acc[4][4];
    #pragma unroll
    for(int i=0;i<4;i++)
      #pragma unroll
      for(int j=0;j<4;j++) acc[i][j]=0.f;
    #pragma unroll 4
    for(int c=0;c<64;c++){
      float4 a = *reinterpret_cast<const float4*>(&sA[c][ty*4]);
      float4 w = *reinterpret_cast<const float4*>(&sW[c][tx*4]);
      acc[0][0]+=a.x*w.x; acc[0][1]+=a.x*w.y; acc[0][2]+=a.x*w.z; acc[0][3]+=a.x*w.w;
      acc[1][0]+=a.y*w.x; acc[1][1]+=a.y*w.y; acc[1][2]+=a.y*w.z; acc[1][3]+=a.y*w.w;
      acc[2][0]+=a.z*w.x; acc[2][1]+=a.z*w.y; acc[2][2]+=a.z*w.z; acc[2][3]+=a.z*w.w;
      acc[3][0]+=a.w*w.x; acc[3][1]+=a.w*w.y; acc[3][2]+=a.w*w.z; acc[3][3]+=a.w*w.w;
    }
    __syncthreads();
    #pragma unroll
    for(int i=0;i<4;i++)
      #pragma unroll
      for(int j=0;j<4;j++)
        sH[(tx*4+j)*68 + ty*4+i] = acc[i][j];
    __syncthreads();
    #pragma unroll
    for(int q=0;q<4;q++){
      int p = (t>>6) + q*4;
      int s0 = p*KNBR - st*64;
      int s1e = s0 + KNBR;
      if(s0 < 0) s0 = 0;
      if(s1e > 64) s1e = 64;
      float mx = rmax[q], mn = rmin[q];
      for(int s=s0; s<s1e; s++){
        float v = sH[myo*68 + s];
        ls1 += v; ls2 += v*v;
        mx = fmaxf(mx, v); mn = fminf(mn, v);
      }
      rmax[q] = mx; rmin[q] = mn;
    }
  }

  #pragma unroll
  for(int q=0;q<4;q++){
    int p = (t>>6) + q*4;
    g_gmax[(pbase+p)*64 + myo] = rmax[q];
    g_gmin[(pbase+p)*64 + myo] = rmin[q];
  }
  r1[t>>6][myo] = ls1;
  r2[t>>6][myo] = ls2;
  __syncthreads();
  if(t < 64){
    atomicAdd(&g_stats2[t],    r1[0][t]+r1[1][t]+r1[2][t]+r1[3][t]);
    atomicAdd(&g_stats2[64+t], r2[0][t]+r2[1][t]+r2[2][t]+r2[3][t]);
  }
}

// ---------------- output ----------------
__global__ void k_out(float* __restrict__ out){
  int n = blockIdx.x*256 + threadIdx.x;
  int o = blockIdx.y, b = blockIdx.z;
  float s = g_scale2[o], tsh = g_shift2[o];
  const float* src = (s >= 0.f) ? g_gmax : g_gmin;
  float v = src[(b*NP + n)*64 + o];
  float h = s*v + tsh;
  out[(b*64 + o)*NP + n] = (h >= 0.f) ? h : 0.2f*h;
}

extern "C" void kernel_launch(void* const* d_in, const int* in_sizes, int n_in,
                              void* d_out, int out_size){
  const float* x  = (const float*)d_in[0];
  const float* W1 = (const float*)d_in[1];
  const float* g1 = (const float*)d_in[2];
  const float* b1 = (const float*)d_in[3];
  const float* W2 = (const float*)d_in[4];
  const float* g2 = (const float*)d_in[5];
  const float* b2 = (const float*)d_in[6];
  float* out = (float*)d_out;

  cudaFuncSetAttribute(k_knn, cudaFuncAttributeMaxDynamicSharedMemorySize, KN5_SMEM);

  k_prep<<<64, 64>>>(W1);
  k_transpose<<<dim3(NP/256, NB), 256>>>(x);
  k_gemm64<<<dim3(NP/64, NB), 256>>>(0);
  k_knn<<<dim3(NP/64, NB), 256, KN5_SMEM>>>(x);
  k_gemm64<<<dim3(NP/64, NB), 256>>>(1);
  k_stats1<<<NSAMP/512, 256>>>();
  k_bnfin<<<1, 64>>>(g1, b1, 0);
  k_conv2<<<NPT/PTS_PER, 256>>>(W2);
  k_bnfin<<<1, 64>>>(g2, b2, 1);
  k_out<<<dim3(NP/256, 64, NB), 256>>>(out);
}